// round 15
// baseline (speedup 1.0000x reference)
#include <cuda_runtime.h>
#include <cuda_bf16.h>
#include <cstdint>

#define BB 16
#define TT 64
#define CC 512

// ---------------------------------------------------------------------------
// Device scratch (allocation-free rule)
// ---------------------------------------------------------------------------
__device__ float g_VE[BB * TT * CC];              // x @ W_proj + b_proj (fp32)
__device__ __nv_bfloat16 g_XEh[BB * TT * CC];     // x @ W_x + b_x (bf16)
__device__ __nv_bfloat16 g_WT[3 * CC * CC];       // [Wim^T | Wp^T | Wx^T] bf16 [N][K]

// ---------------------------------------------------------------------------
// Helpers (baseline sm_80+ PTX: mma.sync / ldmatrix / cp.async / tanh.approx)
// ---------------------------------------------------------------------------
__device__ __forceinline__ uint32_t smem_u32(const void* p) {
    uint32_t a;
    asm("{ .reg .u64 t; cvta.to.shared.u64 t, %1; cvt.u32.u64 %0, t; }" : "=r"(a) : "l"(p));
    return a;
}
__device__ __forceinline__ void ldsm4(uint32_t* r, uint32_t addr) {
    asm volatile("ldmatrix.sync.aligned.m8n8.x4.shared.b16 {%0,%1,%2,%3}, [%4];"
        : "=r"(r[0]), "=r"(r[1]), "=r"(r[2]), "=r"(r[3]) : "r"(addr));
}
__device__ __forceinline__ void mma_bf16(float* d, const uint32_t* a, const uint32_t* b) {
    asm volatile("mma.sync.aligned.m16n8k16.row.col.f32.bf16.bf16.f32 "
        "{%0,%1,%2,%3}, {%4,%5,%6,%7}, {%8,%9}, {%0,%1,%2,%3};"
        : "+f"(d[0]), "+f"(d[1]), "+f"(d[2]), "+f"(d[3])
        : "r"(a[0]), "r"(a[1]), "r"(a[2]), "r"(a[3]), "r"(b[0]), "r"(b[1]));
}
__device__ __forceinline__ void cp_async16(uint32_t dst, const void* src) {
    asm volatile("cp.async.cg.shared.global [%0], [%1], 16;" :: "r"(dst), "l"(src));
}
__device__ __forceinline__ float tanh_fast(float v) {
    float y;
    asm("tanh.approx.f32 %0, %1;" : "=f"(y) : "f"(v));
    return y;
}
__device__ __forceinline__ void bar_grp(int id) {
    asm volatile("bar.sync %0, 128;" :: "r"(id) : "memory");
}
#define CP_COMMIT()  asm volatile("cp.async.commit_group;" ::: "memory")
#define CP_WAIT0()   asm volatile("cp.async.wait_group 0;" ::: "memory")

// temporal smem layout (212992 B total, 1 persistent CTA/SM)
#define OFF_WT0    0           /* [256] bf16x2 packed (1 KB) */
#define OFF_WT1    2048
#define OFF_BT     4096
#define OFF_BIM    6144        /* [512] f32 */
#define OFF_GRP    8192        /* per-group 1536 B */
#define GRP_F0     0           /* [64] bf16x2 broadcast */
#define GRP_F1     256
#define GRP_MASK   512
#define GRP_SOUT2  768
#define GRP_SEXP   1024
#define OFF_A      16384       /* 4 groups x 2 slots x [64 rows][64 k] bf16 (8192 B each) */
#define OFF_B      81920       /* [128 n][512 k] bf16 resident = 131072 */
#define SMEM_BYTES 212992

// embed_mma smem: A [64][512] bf16 = 64 KB, B 2 x 16 KB
#define EMB_OFF_B   65536
#define EMB_SMEM    98304

// ---------------------------------------------------------------------------
// Kernel: transpose + cvt weights to bf16 [N][K]; z==0 blocks also zero out2.
// ---------------------------------------------------------------------------
__global__ void prep_w_kernel(const float* __restrict__ Wim,
                              const float* __restrict__ Wp,
                              const float* __restrict__ Wx,
                              float* __restrict__ out)
{
    __shared__ float tile[32][33];
    const int z = blockIdx.z;
    const float* src = (z == 0) ? Wim : (z == 1) ? Wp : Wx;
    const int n0 = blockIdx.x * 32, k0 = blockIdx.y * 32;
    tile[threadIdx.y][threadIdx.x] = src[(k0 + threadIdx.y) * CC + n0 + threadIdx.x];
    if (z == 0) {
        const int idx = (blockIdx.y * 16 + blockIdx.x) * 256 + threadIdx.y * 32 + threadIdx.x;
        if (idx < BB * TT * TT) out[BB * TT * CC + idx] = 0.f;
    }
    __syncthreads();
    g_WT[(size_t)(z * CC + n0 + threadIdx.y) * CC + k0 + threadIdx.x] =
        __float2bfloat16(tile[threadIdx.x][threadIdx.y]);
}

// ---------------------------------------------------------------------------
// Kernel: embedding GEMMs on tensor cores (unchanged).
// ---------------------------------------------------------------------------
__global__ __launch_bounds__(256, 2) void embed_mma_kernel(
    const float* __restrict__ x,
    const float* __restrict__ bp, const float* __restrict__ bx)
{
    extern __shared__ char sm[];
    const uint32_t smb = smem_u32(sm);
    const int tid = threadIdx.x, lane = tid & 31, wid = tid >> 5;
    const int mt = blockIdx.x & 15, nt = blockIdx.x >> 4;
    const int r0 = mt * 64;

    auto issueB = [&](int s) {
        const int n  = tid >> 1;
        const int cq = (tid & 1) * 4;
        const uint32_t dstRow = smb + EMB_OFF_B + (s & 1) * 16384 + n * 128;
        const __nv_bfloat16* src = g_WT + (size_t)(CC + nt * 128 + n) * CC + s * 64 + cq * 8;
#pragma unroll
        for (int c = 0; c < 4; c++)
            cp_async16(dstRow + (((cq + c) ^ (n & 7)) << 4), src + c * 8);
        CP_COMMIT();
    };
    issueB(0);

    {
        const int rbase = wid * 8;
#pragma unroll
        for (int rr = 0; rr < 8; rr++) {
            const int r = rbase + rr;
            const float* xr = x + (size_t)(r0 + r) * CC;
            char* Arow = sm + r * 1024;
            const int xw = r & 7;
#pragma unroll
            for (int pass = 0; pass < 4; pass++) {
                const int k = pass * 128 + lane * 4;
                const float4 xv = *(const float4*)(xr + k);
                uint2 pk;
                ((__nv_bfloat162*)&pk)[0] = __floats2bfloat162_rn(xv.x, xv.y);
                ((__nv_bfloat162*)&pk)[1] = __floats2bfloat162_rn(xv.z, xv.w);
                const int c8 = pass * 16 + (lane >> 1);
                *(uint2*)(Arow + ((c8 ^ xw) << 4) + ((lane & 1) << 3)) = pk;
            }
        }
    }

    const int mw = wid & 1, nw = wid >> 1;
    const int mA  = mw * 32 + (lane & 15);
    const int aC8 = lane >> 4;
    const int aXr = mA & 7;
    const uint32_t aBase = smb + mA * 1024;
    const int nB  = nw * 32 + (lane & 7) + ((lane >> 4) << 3);
    const int bC8 = (lane >> 3) & 1;
    const int bXr = nB & 7;
    const uint32_t bRowOff = (uint32_t)nB * 128;

    float acc[2][4][4];
#pragma unroll
    for (int mf = 0; mf < 2; mf++)
#pragma unroll
        for (int nf = 0; nf < 4; nf++)
#pragma unroll
            for (int d = 0; d < 4; d++) acc[mf][nf][d] = 0.f;

#pragma unroll 1
    for (int s = 0; s < 8; s++) {
        CP_WAIT0();
        __syncthreads();
        if (s < 7) issueB(s + 1);
        const uint32_t Bslot = smb + EMB_OFF_B + (s & 1) * 16384;
#pragma unroll
        for (int t = 0; t < 4; t++) {
            uint32_t a0[4], a1[4], b0[4], b1[4];
            const uint32_t swA = (uint32_t)(((s * 8 + t * 2 + aC8) ^ aXr) << 4);
            ldsm4(a0, aBase + swA);
            ldsm4(a1, aBase + 16384 + swA);
            const uint32_t swB = (uint32_t)(((t * 2 + bC8) ^ bXr) << 4);
            const uint32_t bA = Bslot + bRowOff + swB;
            ldsm4(b0, bA);
            ldsm4(b1, bA + 2048);
            mma_bf16(acc[0][0], a0, b0);
            mma_bf16(acc[0][1], a0, b0 + 2);
            mma_bf16(acc[0][2], a0, b1);
            mma_bf16(acc[0][3], a0, b1 + 2);
            mma_bf16(acc[1][0], a1, b0);
            mma_bf16(acc[1][1], a1, b0 + 2);
            mma_bf16(acc[1][2], a1, b1);
            mma_bf16(acc[1][3], a1, b1 + 2);
        }
    }

    const int qrow = lane >> 2, qcol2 = (lane & 3) * 2;
    const int cbase = (nt & 3) * 128 + nw * 32;
    const float* bias = (nt < 4) ? bp : bx;
    float2 bb[4];
#pragma unroll
    for (int nf = 0; nf < 4; nf++)
        bb[nf] = *(const float2*)(bias + cbase + nf * 8 + qcol2);

    if (nt < 4) {
#pragma unroll
        for (int mf = 0; mf < 2; mf++)
#pragma unroll
            for (int h = 0; h < 2; h++) {
                const int row = r0 + mw * 32 + mf * 16 + h * 8 + qrow;
#pragma unroll
                for (int nf = 0; nf < 4; nf++) {
                    const int col = cbase + nf * 8 + qcol2;
                    *(float2*)(g_VE + (size_t)row * CC + col) =
                        make_float2(acc[mf][nf][h * 2] + bb[nf].x,
                                    acc[mf][nf][h * 2 + 1] + bb[nf].y);
                }
            }
    } else {
#pragma unroll
        for (int mf = 0; mf < 2; mf++)
#pragma unroll
            for (int h = 0; h < 2; h++) {
                const int row = r0 + mw * 32 + mf * 16 + h * 8 + qrow;
#pragma unroll
                for (int nf = 0; nf < 4; nf++) {
                    const int col = cbase + nf * 8 + qcol2;
                    *(__nv_bfloat162*)(g_XEh + (size_t)row * CC + col) =
                        __floats2bfloat162_rn(acc[mf][nf][h * 2] + bb[nf].x,
                                              acc[mf][nf][h * 2 + 1] + bb[nf].y);
                }
            }
    }
}

// ---------------------------------------------------------------------------
// Main kernel: PERSISTENT, 148 CTAs x 512 threads, 4 independent warpgroups,
// software-pipelined A-build. NEW: packed bf16x2 (HFMA2) A-build + hoisted
// swizzle addresses.
// ---------------------------------------------------------------------------
__global__ __launch_bounds__(512, 1) void temporal_kernel(
    const float* __restrict__ x,
    const float* __restrict__ ts,
    const float* __restrict__ amask,
    const float* __restrict__ Wt,  const float* __restrict__ bt,
    const float* __restrict__ bim,
    float* __restrict__ out)
{
    extern __shared__ char sm[];
    const uint32_t smb = smem_u32(sm);
    const int tid   = threadIdx.x;
    const int lane  = tid & 31;
    const int g     = tid >> 7;          // warpgroup 0..3
    const int wg    = (tid >> 5) & 3;    // warp within group
    const int tid_g = tid & 127;

    const int chunk = blockIdx.x & 3;
    const int slot  = blockIdx.x >> 2;   // 0..36
    const int stream = slot * 4 + g;     // 0..147 within this chunk

    // ---- load resident B slice [128 n][512 k], XOR-swizzled ----
    {
        const __nv_bfloat16* Bsrc = g_WT + (size_t)(chunk * 128) * CC;
#pragma unroll 4
        for (int idx = tid; idx < 8192; idx += 512) {
            const int n = idx >> 6, c8 = idx & 63;
            cp_async16(smb + OFF_B + n * 1024 + ((c8 ^ (n & 7)) << 4),
                       Bsrc + (size_t)n * CC + c8 * 8);
        }
        CP_COMMIT();
    }

    __nv_bfloat162* sWt0h = (__nv_bfloat162*)(sm + OFF_WT0);   // [256]
    __nv_bfloat162* sWt1h = (__nv_bfloat162*)(sm + OFF_WT1);
    __nv_bfloat162* sbth  = (__nv_bfloat162*)(sm + OFF_BT);
    float* sbim = (float*)(sm + OFF_BIM);
    char*  grp  = sm + OFF_GRP + g * 1536;
    uint32_t* f0b  = (uint32_t*)(grp + GRP_F0);   // bf16x2 broadcast
    uint32_t* f1b  = (uint32_t*)(grp + GRP_F1);
    float* maskv = (float*)(grp + GRP_MASK);
    float* sout2 = (float*)(grp + GRP_SOUT2);
    float* sexp  = (float*)(grp + GRP_SEXP);

    sbim[tid] = bim[tid];
    if (tid < 256) {
        sWt0h[tid] = __floats2bfloat162_rn(Wt[tid * 2],      Wt[tid * 2 + 1]);
        sWt1h[tid] = __floats2bfloat162_rn(Wt[CC + tid * 2], Wt[CC + tid * 2 + 1]);
        sbth[tid]  = __floats2bfloat162_rn(bt[tid * 2],      bt[tid * 2 + 1]);
    }
    if (tid_g < 128) sexp[tid_g] = 0.f;
    if (tid_g < 64)  sout2[tid_g] = 0.f;

    CP_WAIT0();
    __syncthreads();   // B + staging visible; groups diverge after this

    // ---- geometry ----
    const int mw = wg & 1, nw = wg >> 1;
    const int m0  = mw * 32;
    const int n0w = nw * 64;
    const int mA  = m0 + (lane & 15);
    const int aC8 = lane >> 4;
    const int aXr = mA & 7;
    const int nB  = n0w + (lane & 7) + ((lane >> 4) << 3);
    const int bC8 = (lane >> 3) & 1;
    const int bXr = nB & 7;
    const uint32_t bBase = smb + OFF_B + (uint32_t)nB * 1024;
    const int qrow = lane >> 2, qcol2 = (lane & 3) * 2;

    // hoisted ldsm swizzle offsets (stage-invariant)
    uint32_t aOff[4], bOff[4];
#pragma unroll
    for (int tk = 0; tk < 4; tk++) {
        aOff[tk] = (uint32_t)(((tk * 2 + aC8) ^ aXr) << 4) + (uint32_t)mA * 128;
        bOff[tk] = bBase + (uint32_t)(((tk * 2 + bC8) ^ bXr) << 4);
    }

    // A-build thread mapping
    const int ro  = tid_g >> 3;          // 0..15
    const int c8b = tid_g & 7;           // k-octet
    char* Ag = sm + OFF_A + g * 16384;   // 2 slots x 8192 B
    const __nv_bfloat162 zero2 = __floats2bfloat162_rn(0.f, 0.f);

    float* gout2 = out + BB * TT * CC;
    const int ntiles = (stream < 136) ? 7 : 6;   // 1024 = 148*6 + 136

    // packed-bf16 A-build for one stage chunk: returns uint4 of 8 h values
    auto buildA = [&](const uint4& xp, uint32_t f0p, uint32_t f1p, int kp) -> uint4 {
        const __nv_bfloat162 f0x2 = *(const __nv_bfloat162*)&f0p;
        const __nv_bfloat162 f1x2 = *(const __nv_bfloat162*)&f1p;
        const uint4 w0q = *(const uint4*)(sWt0h + kp);
        const uint4 w1q = *(const uint4*)(sWt1h + kp);
        const uint4 btq = *(const uint4*)(sbth + kp);
        const __nv_bfloat162* w02 = (const __nv_bfloat162*)&w0q;
        const __nv_bfloat162* w12 = (const __nv_bfloat162*)&w1q;
        const __nv_bfloat162* bt2 = (const __nv_bfloat162*)&btq;
        const __nv_bfloat162* xe2 = (const __nv_bfloat162*)&xp;
        uint4 pk;
        __nv_bfloat162* p2 = (__nv_bfloat162*)&pk;
#pragma unroll
        for (int q = 0; q < 4; q++) {
            __nv_bfloat162 t = __hadd2(bt2[q], xe2[q]);
            t = __hfma2(f1x2, w12[q], t);
            t = __hfma2(f0x2, w02[q], t);
            p2[q] = __hmax2(t, zero2);
        }
        return pk;
    };

#pragma unroll 1
    for (int t = 0; t < ntiles; t++) {
        const int idx = stream + 148 * t;
        const int b = idx >> 6, i = idx & 63;
        const __nv_bfloat16* XEb = g_XEh + (size_t)(b * TT) * CC;

        // ---- per-tile staging ----
        if (tid_g < 64) {
            const float rel = ts[b * TT + i] - ts[b * TT + tid_g];
            const __nv_bfloat16 h0 = __float2bfloat16_rn(log1pf(fmaxf(rel, 0.f)));
            const __nv_bfloat16 h1 = __float2bfloat16_rn(log1pf(fmaxf(-rel, 0.f)));
            __nv_bfloat162 p0 = __nv_bfloat162(h0, h0);
            __nv_bfloat162 p1 = __nv_bfloat162(h1, h1);
            f0b[tid_g] = *(uint32_t*)&p0;
            f1b[tid_g] = *(uint32_t*)&p1;
            maskv[tid_g] = amask[b * TT + tid_g];
        }
        bar_grp(g + 1);

        // ---- build stage 0 into slot 0 ----
        {
            const int kp = c8b * 4;
#pragma unroll
            for (int it = 0; it < 4; it++) {
                const int r = ro + it * 16;
                const uint4 xp = *(const uint4*)(XEb + (size_t)r * CC + c8b * 8);
                const uint4 pk = buildA(xp, f0b[r], f1b[r], kp);
                *(uint4*)(Ag + r * 128 + ((c8b ^ (r & 7)) << 4)) = pk;
            }
        }
        bar_grp(g + 1);

        float acc[2][8][4];
#pragma unroll
        for (int mf = 0; mf < 2; mf++)
#pragma unroll
            for (int nf = 0; nf < 8; nf++)
#pragma unroll
                for (int d = 0; d < 4; d++) acc[mf][nf][d] = 0.f;

        // ---- pipelined stages ----
#pragma unroll 1
        for (int s = 0; s < 8; s++) {
            const uint32_t aSlot = smb + OFF_A + g * 16384 + (s & 1) * 8192;
            const uint32_t bStage = (uint32_t)(s * 128);

            // 1) issue XE loads for stage s+1 (in flight during MMA)
            uint4 xp[4];
            if (s < 7) {
                const int kb = (s + 1) * 64 + c8b * 8;
#pragma unroll
                for (int it = 0; it < 4; it++)
                    xp[it] = *(const uint4*)(XEb + (size_t)(ro + it * 16) * CC + kb);
            }

            // 2) MMA burst for stage s
#pragma unroll
            for (int tk = 0; tk < 4; tk++) {
                uint32_t a0[4], a1[4], bf[4][4];
                const uint32_t aA = aSlot + aOff[tk];
                ldsm4(a0, aA);
                ldsm4(a1, aA + 2048);
                const uint32_t bA = bOff[tk] + bStage;
                ldsm4(bf[0], bA);
                ldsm4(bf[1], bA + 16384);
                ldsm4(bf[2], bA + 32768);
                ldsm4(bf[3], bA + 49152);
#pragma unroll
                for (int qq = 0; qq < 4; qq++) {
                    mma_bf16(acc[0][qq * 2],     a0, bf[qq]);
                    mma_bf16(acc[0][qq * 2 + 1], a0, bf[qq] + 2);
                    mma_bf16(acc[1][qq * 2],     a1, bf[qq]);
                    mma_bf16(acc[1][qq * 2 + 1], a1, bf[qq] + 2);
                }
            }

            // 3) convert + store stage s+1 into the alternate slot
            if (s < 7) {
                const int kp = (s + 1) * 32 + c8b * 4;
                char* Adst = Ag + ((s + 1) & 1) * 8192;
#pragma unroll
                for (int it = 0; it < 4; it++) {
                    const int r = ro + it * 16;
                    const uint4 pk = buildA(xp[it], f0b[r], f1b[r], kp);
                    *(uint4*)(Adst + r * 128 + ((c8b ^ (r & 7)) << 4)) = pk;
                }
            }
            bar_grp(g + 1);
        }

        // ---- register epilogue (two n-halves), group-local reductions ----
        float rs[4] = {0.f, 0.f, 0.f, 0.f};
#pragma unroll
        for (int nh = 0; nh < 2; nh++) {
            float bimv[8], cs[8];
#pragma unroll
            for (int nf = 0; nf < 4; nf++) {
                bimv[nf * 2]     = sbim[chunk * 128 + n0w + nh * 32 + nf * 8 + qcol2];
                bimv[nf * 2 + 1] = sbim[chunk * 128 + n0w + nh * 32 + nf * 8 + qcol2 + 1];
                cs[nf * 2] = 0.f; cs[nf * 2 + 1] = 0.f;
            }
#pragma unroll
            for (int mf = 0; mf < 2; mf++) {
#pragma unroll
                for (int h = 0; h < 2; h++) {
                    const int r  = m0 + mf * 16 + h * 8 + qrow;
                    const float hmk = 0.5f * maskv[r];
                    const float* VEr = g_VE + (size_t)(b * TT + r) * CC
                                       + chunk * 128 + n0w + nh * 32 + qcol2;
                    float rsum = 0.f;
#pragma unroll
                    for (int nf = 0; nf < 4; nf++) {
                        const float2 ve = *(const float2*)(VEr + nf * 8);
                        const float s0 = acc[mf][nh * 4 + nf][h * 2 + 0] + bimv[nf * 2];
                        const float s1 = acc[mf][nh * 4 + nf][h * 2 + 1] + bimv[nf * 2 + 1];
                        const float p0 = fmaf(tanh_fast(0.5f * s0), hmk, hmk);
                        const float p1 = fmaf(tanh_fast(0.5f * s1), hmk, hmk);
                        rsum += p0 + p1;
                        cs[nf * 2]     += __expf(ve.x * p0);
                        cs[nf * 2 + 1] += __expf(ve.y * p1);
                    }
                    rs[mf * 2 + h] += rsum;
                }
            }
#pragma unroll
            for (int c = 0; c < 8; c++) {
                cs[c] += __shfl_xor_sync(0xffffffffu, cs[c], 4);
                cs[c] += __shfl_xor_sync(0xffffffffu, cs[c], 8);
                cs[c] += __shfl_xor_sync(0xffffffffu, cs[c], 16);
            }
            if (lane < 4) {
#pragma unroll
                for (int nf = 0; nf < 4; nf++) {
                    atomicAdd(&sexp[n0w + nh * 32 + nf * 8 + lane * 2],     cs[nf * 2]);
                    atomicAdd(&sexp[n0w + nh * 32 + nf * 8 + lane * 2 + 1], cs[nf * 2 + 1]);
                }
            }
        }
#pragma unroll
        for (int q = 0; q < 4; q++) {
            rs[q] += __shfl_xor_sync(0xffffffffu, rs[q], 1);
            rs[q] += __shfl_xor_sync(0xffffffffu, rs[q], 2);
        }
        if ((lane & 3) == 0) {
#pragma unroll
            for (int q = 0; q < 4; q++)
                atomicAdd(&sout2[m0 + (q >> 1) * 16 + (q & 1) * 8 + qrow], rs[q]);
        }
        bar_grp(g + 1);

        // ---- outputs ----
        if (tid_g < 128) {
            const int ng = chunk * 128 + tid_g;
            const int row = b * TT + i;
            out[(size_t)row * CC + ng] = x[(size_t)row * CC + ng] + __logf(sexp[tid_g]);
            sexp[tid_g] = 0.f;
        }
        if (tid_g < 64) {
            atomicAdd(&gout2[(b * TT + i) * TT + tid_g], sout2[tid_g] * (1.f / 512.f));
            sout2[tid_g] = 0.f;
        }
        bar_grp(g + 1);
    }
}

// ---------------------------------------------------------------------------
extern "C" void kernel_launch(void* const* d_in, const int* in_sizes, int n_in,
                              void* d_out, int out_size)
{
    const float* x     = (const float*)d_in[0];
    const float* ts    = (const float*)d_in[1];
    const float* amask = (const float*)d_in[2];
    const float* Wp    = (const float*)d_in[3];
    const float* bp    = (const float*)d_in[4];
    const float* Wx    = (const float*)d_in[5];
    const float* bx    = (const float*)d_in[6];
    const float* Wt    = (const float*)d_in[7];
    const float* bt    = (const float*)d_in[8];
    const float* Wim   = (const float*)d_in[9];
    const float* bim   = (const float*)d_in[10];
    float* out = (float*)d_out;

    prep_w_kernel<<<dim3(16, 16, 3), dim3(32, 32)>>>(Wim, Wp, Wx, out);

    cudaFuncSetAttribute(embed_mma_kernel, cudaFuncAttributeMaxDynamicSharedMemorySize, EMB_SMEM);
    embed_mma_kernel<<<128, 256, EMB_SMEM>>>(x, bp, bx);

    cudaFuncSetAttribute(temporal_kernel, cudaFuncAttributeMaxDynamicSharedMemorySize, SMEM_BYTES);
    temporal_kernel<<<148, 512, SMEM_BYTES>>>(x, ts, amask, Wt, bt, bim, out);
}

// round 16
// speedup vs baseline: 1.0233x; 1.0233x over previous
#include <cuda_runtime.h>
#include <cuda_bf16.h>
#include <cstdint>

#define BB 16
#define TT 64
#define CC 512

// ---------------------------------------------------------------------------
// Device scratch (allocation-free rule)
// ---------------------------------------------------------------------------
__device__ float g_VE[BB * TT * CC];              // (x @ W_proj + b_proj) * log2e
__device__ __nv_bfloat16 g_XEh[BB * TT * CC];     // x @ W_x + b_x (bf16)
__device__ __nv_bfloat16 g_WT[3 * CC * CC];       // [Wim^T | Wp^T | Wx^T] bf16 [N][K]

// ---------------------------------------------------------------------------
// Helpers (baseline sm_80+ PTX: mma.sync / ldmatrix / cp.async / tanh.approx)
// ---------------------------------------------------------------------------
__device__ __forceinline__ uint32_t smem_u32(const void* p) {
    uint32_t a;
    asm("{ .reg .u64 t; cvta.to.shared.u64 t, %1; cvt.u32.u64 %0, t; }" : "=r"(a) : "l"(p));
    return a;
}
__device__ __forceinline__ void ldsm4(uint32_t* r, uint32_t addr) {
    asm volatile("ldmatrix.sync.aligned.m8n8.x4.shared.b16 {%0,%1,%2,%3}, [%4];"
        : "=r"(r[0]), "=r"(r[1]), "=r"(r[2]), "=r"(r[3]) : "r"(addr));
}
__device__ __forceinline__ void mma_bf16(float* d, const uint32_t* a, const uint32_t* b) {
    asm volatile("mma.sync.aligned.m16n8k16.row.col.f32.bf16.bf16.f32 "
        "{%0,%1,%2,%3}, {%4,%5,%6,%7}, {%8,%9}, {%0,%1,%2,%3};"
        : "+f"(d[0]), "+f"(d[1]), "+f"(d[2]), "+f"(d[3])
        : "r"(a[0]), "r"(a[1]), "r"(a[2]), "r"(a[3]), "r"(b[0]), "r"(b[1]));
}
__device__ __forceinline__ void cp_async16(uint32_t dst, const void* src) {
    asm volatile("cp.async.cg.shared.global [%0], [%1], 16;" :: "r"(dst), "l"(src));
}
__device__ __forceinline__ float tanh_fast(float v) {
    float y;
    asm("tanh.approx.f32 %0, %1;" : "=f"(y) : "f"(v));
    return y;
}
__device__ __forceinline__ float ex2_fast(float v) {
    float y;
    asm("ex2.approx.f32 %0, %1;" : "=f"(y) : "f"(v));
    return y;
}
__device__ __forceinline__ void bar_grp(int id) {
    asm volatile("bar.sync %0, 128;" :: "r"(id) : "memory");
}
#define CP_COMMIT()  asm volatile("cp.async.commit_group;" ::: "memory")
#define CP_WAIT0()   asm volatile("cp.async.wait_group 0;" ::: "memory")

// temporal smem layout (212992 B total, 1 persistent CTA/SM)
#define OFF_WT0    0           /* [256] bf16x2 packed (1 KB) */
#define OFF_WT1    2048
#define OFF_BT     4096
#define OFF_BIM    6144        /* [512] f32 */
#define OFF_GRP    8192        /* per-group 1536 B */
#define GRP_F0     0           /* [64] bf16x2 broadcast */
#define GRP_F1     256
#define GRP_MASK   512
#define GRP_SOUT2  768
#define GRP_SEXP   1024
#define OFF_A      16384       /* 4 groups x 2 slots x [64 rows][64 k] bf16 (8192 B each) */
#define OFF_B      81920       /* [128 n][512 k] bf16 resident = 131072 */
#define SMEM_BYTES 212992

// embed_mma smem: A [64][512] bf16 = 64 KB, B 2 x 16 KB
#define EMB_OFF_B   65536
#define EMB_SMEM    98304

#define LOG2E 1.4426950408889634f

// ---------------------------------------------------------------------------
// Kernel: transpose + cvt weights to bf16 [N][K]; z==0 blocks also zero out2.
// ---------------------------------------------------------------------------
__global__ void prep_w_kernel(const float* __restrict__ Wim,
                              const float* __restrict__ Wp,
                              const float* __restrict__ Wx,
                              float* __restrict__ out)
{
    __shared__ float tile[32][33];
    const int z = blockIdx.z;
    const float* src = (z == 0) ? Wim : (z == 1) ? Wp : Wx;
    const int n0 = blockIdx.x * 32, k0 = blockIdx.y * 32;
    tile[threadIdx.y][threadIdx.x] = src[(k0 + threadIdx.y) * CC + n0 + threadIdx.x];
    if (z == 0) {
        const int idx = (blockIdx.y * 16 + blockIdx.x) * 256 + threadIdx.y * 32 + threadIdx.x;
        if (idx < BB * TT * TT) out[BB * TT * CC + idx] = 0.f;
    }
    __syncthreads();
    g_WT[(size_t)(z * CC + n0 + threadIdx.y) * CC + k0 + threadIdx.x] =
        __float2bfloat16(tile[threadIdx.x][threadIdx.y]);
}

// ---------------------------------------------------------------------------
// Kernel: embedding GEMMs on tensor cores. VE is pre-scaled by log2e.
// ---------------------------------------------------------------------------
__global__ __launch_bounds__(256, 2) void embed_mma_kernel(
    const float* __restrict__ x,
    const float* __restrict__ bp, const float* __restrict__ bx)
{
    extern __shared__ char sm[];
    const uint32_t smb = smem_u32(sm);
    const int tid = threadIdx.x, lane = tid & 31, wid = tid >> 5;
    const int mt = blockIdx.x & 15, nt = blockIdx.x >> 4;
    const int r0 = mt * 64;

    auto issueB = [&](int s) {
        const int n  = tid >> 1;
        const int cq = (tid & 1) * 4;
        const uint32_t dstRow = smb + EMB_OFF_B + (s & 1) * 16384 + n * 128;
        const __nv_bfloat16* src = g_WT + (size_t)(CC + nt * 128 + n) * CC + s * 64 + cq * 8;
#pragma unroll
        for (int c = 0; c < 4; c++)
            cp_async16(dstRow + (((cq + c) ^ (n & 7)) << 4), src + c * 8);
        CP_COMMIT();
    };
    issueB(0);

    {
        const int rbase = wid * 8;
#pragma unroll
        for (int rr = 0; rr < 8; rr++) {
            const int r = rbase + rr;
            const float* xr = x + (size_t)(r0 + r) * CC;
            char* Arow = sm + r * 1024;
            const int xw = r & 7;
#pragma unroll
            for (int pass = 0; pass < 4; pass++) {
                const int k = pass * 128 + lane * 4;
                const float4 xv = *(const float4*)(xr + k);
                uint2 pk;
                ((__nv_bfloat162*)&pk)[0] = __floats2bfloat162_rn(xv.x, xv.y);
                ((__nv_bfloat162*)&pk)[1] = __floats2bfloat162_rn(xv.z, xv.w);
                const int c8 = pass * 16 + (lane >> 1);
                *(uint2*)(Arow + ((c8 ^ xw) << 4) + ((lane & 1) << 3)) = pk;
            }
        }
    }

    const int mw = wid & 1, nw = wid >> 1;
    const int mA  = mw * 32 + (lane & 15);
    const int aC8 = lane >> 4;
    const int aXr = mA & 7;
    const uint32_t aBase = smb + mA * 1024;
    const int nB  = nw * 32 + (lane & 7) + ((lane >> 4) << 3);
    const int bC8 = (lane >> 3) & 1;
    const int bXr = nB & 7;
    const uint32_t bRowOff = (uint32_t)nB * 128;

    float acc[2][4][4];
#pragma unroll
    for (int mf = 0; mf < 2; mf++)
#pragma unroll
        for (int nf = 0; nf < 4; nf++)
#pragma unroll
            for (int d = 0; d < 4; d++) acc[mf][nf][d] = 0.f;

#pragma unroll 1
    for (int s = 0; s < 8; s++) {
        CP_WAIT0();
        __syncthreads();
        if (s < 7) issueB(s + 1);
        const uint32_t Bslot = smb + EMB_OFF_B + (s & 1) * 16384;
#pragma unroll
        for (int t = 0; t < 4; t++) {
            uint32_t a0[4], a1[4], b0[4], b1[4];
            const uint32_t swA = (uint32_t)(((s * 8 + t * 2 + aC8) ^ aXr) << 4);
            ldsm4(a0, aBase + swA);
            ldsm4(a1, aBase + 16384 + swA);
            const uint32_t swB = (uint32_t)(((t * 2 + bC8) ^ bXr) << 4);
            const uint32_t bA = Bslot + bRowOff + swB;
            ldsm4(b0, bA);
            ldsm4(b1, bA + 2048);
            mma_bf16(acc[0][0], a0, b0);
            mma_bf16(acc[0][1], a0, b0 + 2);
            mma_bf16(acc[0][2], a0, b1);
            mma_bf16(acc[0][3], a0, b1 + 2);
            mma_bf16(acc[1][0], a1, b0);
            mma_bf16(acc[1][1], a1, b0 + 2);
            mma_bf16(acc[1][2], a1, b1);
            mma_bf16(acc[1][3], a1, b1 + 2);
        }
    }

    const int qrow = lane >> 2, qcol2 = (lane & 3) * 2;
    const int cbase = (nt & 3) * 128 + nw * 32;
    const float* bias = (nt < 4) ? bp : bx;
    float2 bb[4];
#pragma unroll
    for (int nf = 0; nf < 4; nf++)
        bb[nf] = *(const float2*)(bias + cbase + nf * 8 + qcol2);

    if (nt < 4) {
#pragma unroll
        for (int mf = 0; mf < 2; mf++)
#pragma unroll
            for (int h = 0; h < 2; h++) {
                const int row = r0 + mw * 32 + mf * 16 + h * 8 + qrow;
#pragma unroll
                for (int nf = 0; nf < 4; nf++) {
                    const int col = cbase + nf * 8 + qcol2;
                    *(float2*)(g_VE + (size_t)row * CC + col) =
                        make_float2((acc[mf][nf][h * 2] + bb[nf].x) * LOG2E,
                                    (acc[mf][nf][h * 2 + 1] + bb[nf].y) * LOG2E);
                }
            }
    } else {
#pragma unroll
        for (int mf = 0; mf < 2; mf++)
#pragma unroll
            for (int h = 0; h < 2; h++) {
                const int row = r0 + mw * 32 + mf * 16 + h * 8 + qrow;
#pragma unroll
                for (int nf = 0; nf < 4; nf++) {
                    const int col = cbase + nf * 8 + qcol2;
                    *(__nv_bfloat162*)(g_XEh + (size_t)row * CC + col) =
                        __floats2bfloat162_rn(acc[mf][nf][h * 2] + bb[nf].x,
                                              acc[mf][nf][h * 2 + 1] + bb[nf].y);
                }
            }
    }
}

// ---------------------------------------------------------------------------
// Main kernel: PERSISTENT, 148 CTAs x 512 threads, 4 independent warpgroups,
// software-pipelined A-build, packed bf16x2 build. NEW: deliberate per-group
// phase stagger so converts/epilogues overlap other groups' MMA bursts;
// exp via raw ex2 on pre-scaled VE.
// ---------------------------------------------------------------------------
__global__ __launch_bounds__(512, 1) void temporal_kernel(
    const float* __restrict__ x,
    const float* __restrict__ ts,
    const float* __restrict__ amask,
    const float* __restrict__ Wt,  const float* __restrict__ bt,
    const float* __restrict__ bim,
    float* __restrict__ out)
{
    extern __shared__ char sm[];
    const uint32_t smb = smem_u32(sm);
    const int tid   = threadIdx.x;
    const int lane  = tid & 31;
    const int g     = tid >> 7;          // warpgroup 0..3
    const int wg    = (tid >> 5) & 3;    // warp within group
    const int tid_g = tid & 127;

    const int chunk = blockIdx.x & 3;
    const int slot  = blockIdx.x >> 2;   // 0..36
    const int stream = slot * 4 + g;     // 0..147 within this chunk

    // ---- load resident B slice [128 n][512 k], XOR-swizzled ----
    {
        const __nv_bfloat16* Bsrc = g_WT + (size_t)(chunk * 128) * CC;
#pragma unroll 4
        for (int idx = tid; idx < 8192; idx += 512) {
            const int n = idx >> 6, c8 = idx & 63;
            cp_async16(smb + OFF_B + n * 1024 + ((c8 ^ (n & 7)) << 4),
                       Bsrc + (size_t)n * CC + c8 * 8);
        }
        CP_COMMIT();
    }

    __nv_bfloat162* sWt0h = (__nv_bfloat162*)(sm + OFF_WT0);   // [256]
    __nv_bfloat162* sWt1h = (__nv_bfloat162*)(sm + OFF_WT1);
    __nv_bfloat162* sbth  = (__nv_bfloat162*)(sm + OFF_BT);
    float* sbim = (float*)(sm + OFF_BIM);
    char*  grp  = sm + OFF_GRP + g * 1536;
    uint32_t* f0b  = (uint32_t*)(grp + GRP_F0);   // bf16x2 broadcast
    uint32_t* f1b  = (uint32_t*)(grp + GRP_F1);
    float* maskv = (float*)(grp + GRP_MASK);
    float* sout2 = (float*)(grp + GRP_SOUT2);
    float* sexp  = (float*)(grp + GRP_SEXP);

    sbim[tid] = bim[tid];
    if (tid < 256) {
        sWt0h[tid] = __floats2bfloat162_rn(Wt[tid * 2],      Wt[tid * 2 + 1]);
        sWt1h[tid] = __floats2bfloat162_rn(Wt[CC + tid * 2], Wt[CC + tid * 2 + 1]);
        sbth[tid]  = __floats2bfloat162_rn(bt[tid * 2],      bt[tid * 2 + 1]);
    }
    if (tid_g < 128) sexp[tid_g] = 0.f;
    if (tid_g < 64)  sout2[tid_g] = 0.f;

    CP_WAIT0();
    __syncthreads();   // B + staging visible; groups diverge after this

    // ---- phase stagger: offset each group's pipeline in TIME so that
    //      converts/epilogues overlap other groups' MMA bursts ----
    if (g > 0) {
        const unsigned delay = (unsigned)g * 1800u;
        const unsigned t0 = (unsigned)clock();
        while ((unsigned)clock() - t0 < delay) { }
    }

    // ---- geometry ----
    const int mw = wg & 1, nw = wg >> 1;
    const int m0  = mw * 32;
    const int n0w = nw * 64;
    const int mA  = m0 + (lane & 15);
    const int aC8 = lane >> 4;
    const int aXr = mA & 7;
    const int nB  = n0w + (lane & 7) + ((lane >> 4) << 3);
    const int bC8 = (lane >> 3) & 1;
    const int bXr = nB & 7;
    const uint32_t bBase = smb + OFF_B + (uint32_t)nB * 1024;
    const int qrow = lane >> 2, qcol2 = (lane & 3) * 2;

    // hoisted ldsm swizzle offsets (stage-invariant)
    uint32_t aOff[4], bOff[4];
#pragma unroll
    for (int tk = 0; tk < 4; tk++) {
        aOff[tk] = (uint32_t)(((tk * 2 + aC8) ^ aXr) << 4) + (uint32_t)mA * 128;
        bOff[tk] = bBase + (uint32_t)(((tk * 2 + bC8) ^ bXr) << 4);
    }

    // A-build thread mapping
    const int ro  = tid_g >> 3;          // 0..15
    const int c8b = tid_g & 7;           // k-octet
    char* Ag = sm + OFF_A + g * 16384;   // 2 slots x 8192 B
    const __nv_bfloat162 zero2 = __floats2bfloat162_rn(0.f, 0.f);

    float* gout2 = out + BB * TT * CC;
    const int ntiles = (stream < 136) ? 7 : 6;   // 1024 = 148*6 + 136

    // packed-bf16 A-build for one stage chunk: returns uint4 of 8 h values
    auto buildA = [&](const uint4& xp, uint32_t f0p, uint32_t f1p, int kp) -> uint4 {
        const __nv_bfloat162 f0x2 = *(const __nv_bfloat162*)&f0p;
        const __nv_bfloat162 f1x2 = *(const __nv_bfloat162*)&f1p;
        const uint4 w0q = *(const uint4*)(sWt0h + kp);
        const uint4 w1q = *(const uint4*)(sWt1h + kp);
        const uint4 btq = *(const uint4*)(sbth + kp);
        const __nv_bfloat162* w02 = (const __nv_bfloat162*)&w0q;
        const __nv_bfloat162* w12 = (const __nv_bfloat162*)&w1q;
        const __nv_bfloat162* bt2 = (const __nv_bfloat162*)&btq;
        const __nv_bfloat162* xe2 = (const __nv_bfloat162*)&xp;
        uint4 pk;
        __nv_bfloat162* p2 = (__nv_bfloat162*)&pk;
#pragma unroll
        for (int q = 0; q < 4; q++) {
            __nv_bfloat162 t = __hadd2(bt2[q], xe2[q]);
            t = __hfma2(f1x2, w12[q], t);
            t = __hfma2(f0x2, w02[q], t);
            p2[q] = __hmax2(t, zero2);
        }
        return pk;
    };

#pragma unroll 1
    for (int t = 0; t < ntiles; t++) {
        const int idx = stream + 148 * t;
        const int b = idx >> 6, i = idx & 63;
        const __nv_bfloat16* XEb = g_XEh + (size_t)(b * TT) * CC;

        // ---- per-tile staging ----
        if (tid_g < 64) {
            const float rel = ts[b * TT + i] - ts[b * TT + tid_g];
            const __nv_bfloat16 h0 = __float2bfloat16_rn(log1pf(fmaxf(rel, 0.f)));
            const __nv_bfloat16 h1 = __float2bfloat16_rn(log1pf(fmaxf(-rel, 0.f)));
            __nv_bfloat162 p0 = __nv_bfloat162(h0, h0);
            __nv_bfloat162 p1 = __nv_bfloat162(h1, h1);
            f0b[tid_g] = *(uint32_t*)&p0;
            f1b[tid_g] = *(uint32_t*)&p1;
            maskv[tid_g] = amask[b * TT + tid_g];
        }
        bar_grp(g + 1);

        // ---- build stage 0 into slot 0 ----
        {
            const int kp = c8b * 4;
#pragma unroll
            for (int it = 0; it < 4; it++) {
                const int r = ro + it * 16;
                const uint4 xp = *(const uint4*)(XEb + (size_t)r * CC + c8b * 8);
                const uint4 pk = buildA(xp, f0b[r], f1b[r], kp);
                *(uint4*)(Ag + r * 128 + ((c8b ^ (r & 7)) << 4)) = pk;
            }
        }
        bar_grp(g + 1);

        float acc[2][8][4];
#pragma unroll
        for (int mf = 0; mf < 2; mf++)
#pragma unroll
            for (int nf = 0; nf < 8; nf++)
#pragma unroll
                for (int d = 0; d < 4; d++) acc[mf][nf][d] = 0.f;

        // ---- pipelined stages ----
#pragma unroll 1
        for (int s = 0; s < 8; s++) {
            const uint32_t aSlot = smb + OFF_A + g * 16384 + (s & 1) * 8192;
            const uint32_t bStage = (uint32_t)(s * 128);

            // 1) issue XE loads for stage s+1 (in flight during MMA)
            uint4 xp[4];
            if (s < 7) {
                const int kb = (s + 1) * 64 + c8b * 8;
#pragma unroll
                for (int it = 0; it < 4; it++)
                    xp[it] = *(const uint4*)(XEb + (size_t)(ro + it * 16) * CC + kb);
            }

            // 2) MMA burst for stage s
#pragma unroll
            for (int tk = 0; tk < 4; tk++) {
                uint32_t a0[4], a1[4], bf[4][4];
                const uint32_t aA = aSlot + aOff[tk];
                ldsm4(a0, aA);
                ldsm4(a1, aA + 2048);
                const uint32_t bA = bOff[tk] + bStage;
                ldsm4(bf[0], bA);
                ldsm4(bf[1], bA + 16384);
                ldsm4(bf[2], bA + 32768);
                ldsm4(bf[3], bA + 49152);
#pragma unroll
                for (int qq = 0; qq < 4; qq++) {
                    mma_bf16(acc[0][qq * 2],     a0, bf[qq]);
                    mma_bf16(acc[0][qq * 2 + 1], a0, bf[qq] + 2);
                    mma_bf16(acc[1][qq * 2],     a1, bf[qq]);
                    mma_bf16(acc[1][qq * 2 + 1], a1, bf[qq] + 2);
                }
            }

            // 3) convert + store stage s+1 into the alternate slot
            if (s < 7) {
                const int kp = (s + 1) * 32 + c8b * 4;
                char* Adst = Ag + ((s + 1) & 1) * 8192;
#pragma unroll
                for (int it = 0; it < 4; it++) {
                    const int r = ro + it * 16;
                    const uint4 pk = buildA(xp[it], f0b[r], f1b[r], kp);
                    *(uint4*)(Adst + r * 128 + ((c8b ^ (r & 7)) << 4)) = pk;
                }
            }
            bar_grp(g + 1);
        }

        // ---- register epilogue (two n-halves), group-local reductions ----
        float rs[4] = {0.f, 0.f, 0.f, 0.f};
#pragma unroll
        for (int nh = 0; nh < 2; nh++) {
            float bimv[8], cs[8];
#pragma unroll
            for (int nf = 0; nf < 4; nf++) {
                bimv[nf * 2]     = sbim[chunk * 128 + n0w + nh * 32 + nf * 8 + qcol2];
                bimv[nf * 2 + 1] = sbim[chunk * 128 + n0w + nh * 32 + nf * 8 + qcol2 + 1];
                cs[nf * 2] = 0.f; cs[nf * 2 + 1] = 0.f;
            }
#pragma unroll
            for (int mf = 0; mf < 2; mf++) {
#pragma unroll
                for (int h = 0; h < 2; h++) {
                    const int r  = m0 + mf * 16 + h * 8 + qrow;
                    const float hmk = 0.5f * maskv[r];
                    const float* VEr = g_VE + (size_t)(b * TT + r) * CC
                                       + chunk * 128 + n0w + nh * 32 + qcol2;
                    float rsum = 0.f;
#pragma unroll
                    for (int nf = 0; nf < 4; nf++) {
                        const float2 ve = *(const float2*)(VEr + nf * 8);
                        const float s0 = acc[mf][nh * 4 + nf][h * 2 + 0] + bimv[nf * 2];
                        const float s1 = acc[mf][nh * 4 + nf][h * 2 + 1] + bimv[nf * 2 + 1];
                        const float p0 = fmaf(tanh_fast(0.5f * s0), hmk, hmk);
                        const float p1 = fmaf(tanh_fast(0.5f * s1), hmk, hmk);
                        rsum += p0 + p1;
                        cs[nf * 2]     += ex2_fast(ve.x * p0);   // VE pre-scaled by log2e
                        cs[nf * 2 + 1] += ex2_fast(ve.y * p1);
                    }
                    rs[mf * 2 + h] += rsum;
                }
            }
#pragma unroll
            for (int c = 0; c < 8; c++) {
                cs[c] += __shfl_xor_sync(0xffffffffu, cs[c], 4);
                cs[c] += __shfl_xor_sync(0xffffffffu, cs[c], 8);
                cs[c] += __shfl_xor_sync(0xffffffffu, cs[c], 16);
            }
            if (lane < 4) {
#pragma unroll
                for (int nf = 0; nf < 4; nf++) {
                    atomicAdd(&sexp[n0w + nh * 32 + nf * 8 + lane * 2],     cs[nf * 2]);
                    atomicAdd(&sexp[n0w + nh * 32 + nf * 8 + lane * 2 + 1], cs[nf * 2 + 1]);
                }
            }
        }
#pragma unroll
        for (int q = 0; q < 4; q++) {
            rs[q] += __shfl_xor_sync(0xffffffffu, rs[q], 1);
            rs[q] += __shfl_xor_sync(0xffffffffu, rs[q], 2);
        }
        if ((lane & 3) == 0) {
#pragma unroll
            for (int q = 0; q < 4; q++)
                atomicAdd(&sout2[m0 + (q >> 1) * 16 + (q & 1) * 8 + qrow], rs[q]);
        }
        bar_grp(g + 1);

        // ---- outputs ----
        if (tid_g < 128) {
            const int ng = chunk * 128 + tid_g;
            const int row = b * TT + i;
            out[(size_t)row * CC + ng] = x[(size_t)row * CC + ng] + __logf(sexp[tid_g]);
            sexp[tid_g] = 0.f;
        }
        if (tid_g < 64) {
            atomicAdd(&gout2[(b * TT + i) * TT + tid_g], sout2[tid_g] * (1.f / 512.f));
            sout2[tid_g] = 0.f;
        }
        bar_grp(g + 1);
    }
}

// ---------------------------------------------------------------------------
extern "C" void kernel_launch(void* const* d_in, const int* in_sizes, int n_in,
                              void* d_out, int out_size)
{
    const float* x     = (const float*)d_in[0];
    const float* ts    = (const float*)d_in[1];
    const float* amask = (const float*)d_in[2];
    const float* Wp    = (const float*)d_in[3];
    const float* bp    = (const float*)d_in[4];
    const float* Wx    = (const float*)d_in[5];
    const float* bx    = (const float*)d_in[6];
    const float* Wt    = (const float*)d_in[7];
    const float* bt    = (const float*)d_in[8];
    const float* Wim   = (const float*)d_in[9];
    const float* bim   = (const float*)d_in[10];
    float* out = (float*)d_out;

    prep_w_kernel<<<dim3(16, 16, 3), dim3(32, 32)>>>(Wim, Wp, Wx, out);

    cudaFuncSetAttribute(embed_mma_kernel, cudaFuncAttributeMaxDynamicSharedMemorySize, EMB_SMEM);
    embed_mma_kernel<<<128, 256, EMB_SMEM>>>(x, bp, bx);

    cudaFuncSetAttribute(temporal_kernel, cudaFuncAttributeMaxDynamicSharedMemorySize, SMEM_BYTES);
    temporal_kernel<<<148, 512, SMEM_BYTES>>>(x, ts, amask, Wt, bt, bim, out);
}

// round 17
// speedup vs baseline: 1.0789x; 1.0543x over previous
#include <cuda_runtime.h>
#include <cuda_bf16.h>
#include <cstdint>

#define BB 16
#define TT 64
#define CC 512

// ---------------------------------------------------------------------------
// Device scratch (allocation-free rule)
// ---------------------------------------------------------------------------
__device__ float g_VE[BB * TT * CC];              // (x @ W_proj + b_proj) * log2e
__device__ __nv_bfloat16 g_XEh[BB * TT * CC];     // x @ W_x + b_x (bf16)
__device__ __nv_bfloat16 g_WT[3 * CC * CC];       // [Wim^T | Wp^T | Wx^T] bf16 [N][K]

// ---------------------------------------------------------------------------
// Helpers (baseline sm_80+ PTX: mma.sync / ldmatrix / cp.async / mbarrier)
// ---------------------------------------------------------------------------
__device__ __forceinline__ uint32_t smem_u32(const void* p) {
    uint32_t a;
    asm("{ .reg .u64 t; cvta.to.shared.u64 t, %1; cvt.u32.u64 %0, t; }" : "=r"(a) : "l"(p));
    return a;
}
__device__ __forceinline__ void ldsm4(uint32_t* r, uint32_t addr) {
    asm volatile("ldmatrix.sync.aligned.m8n8.x4.shared.b16 {%0,%1,%2,%3}, [%4];"
        : "=r"(r[0]), "=r"(r[1]), "=r"(r[2]), "=r"(r[3]) : "r"(addr));
}
__device__ __forceinline__ void mma_bf16(float* d, const uint32_t* a, const uint32_t* b) {
    asm volatile("mma.sync.aligned.m16n8k16.row.col.f32.bf16.bf16.f32 "
        "{%0,%1,%2,%3}, {%4,%5,%6,%7}, {%8,%9}, {%0,%1,%2,%3};"
        : "+f"(d[0]), "+f"(d[1]), "+f"(d[2]), "+f"(d[3])
        : "r"(a[0]), "r"(a[1]), "r"(a[2]), "r"(a[3]), "r"(b[0]), "r"(b[1]));
}
__device__ __forceinline__ void cp_async16(uint32_t dst, const void* src) {
    asm volatile("cp.async.cg.shared.global [%0], [%1], 16;" :: "r"(dst), "l"(src));
}
__device__ __forceinline__ float tanh_fast(float v) {
    float y;
    asm("tanh.approx.f32 %0, %1;" : "=f"(y) : "f"(v));
    return y;
}
__device__ __forceinline__ float ex2_fast(float v) {
    float y;
    asm("ex2.approx.f32 %0, %1;" : "=f"(y) : "f"(v));
    return y;
}
__device__ __forceinline__ void bar_named(int id, int nthr) {
    asm volatile("bar.sync %0, %1;" :: "r"(id), "r"(nthr) : "memory");
}
#define CP_COMMIT()  asm volatile("cp.async.commit_group;" ::: "memory")
#define CP_WAIT0()   asm volatile("cp.async.wait_group 0;" ::: "memory")

#define MBAR_INIT(mb, c) asm volatile("mbarrier.init.shared.b64 [%0], %1;" :: "r"(mb), "r"((uint32_t)(c)) : "memory")
#define MBAR_ARRIVE(mb)  asm volatile("mbarrier.arrive.shared.b64 _, [%0];" :: "r"(mb) : "memory")

__device__ __forceinline__ void mbar_wait(uint32_t mb, int phase) {
    asm volatile(
        "{\n\t.reg .pred P1;\n\t"
        "WL%=:\n\t"
        "mbarrier.try_wait.parity.acquire.cta.shared::cta.b64 P1, [%0], %1, 0x989680;\n\t"
        "@P1 bra WD%=;\n\tbra WL%=;\n\tWD%=:\n\t}"
        :: "r"(mb), "r"((uint32_t)phase) : "memory");
}

// temporal smem layout (205312 B total, 1 persistent CTA/SM)
#define OFF_WT0    0           /* [256] bf16x2 (1 KB) */
#define OFF_WT1    1024
#define OFF_BT     2048
#define OFF_BIM    3072        /* [512] f32 */
#define OFF_MBAR   5120        /* 2 groups x 4 slots x (full,empty) x 8 B = 128 */
#define OFF_GRP    5376        /* per-group 1536 B */
#define GRP_F0     0           /* [64] u32 bf16x2 broadcast (builders only) */
#define GRP_F1     256
#define GRP_SOUT2  512
#define GRP_SEXP   768         /* [128] f32 */
#define OFF_A      8704        /* 2 groups x 4 slots x 8192 B = 65536 */
#define OFF_B      74240       /* [128 n][512 k] bf16 resident = 131072 */
#define SMEM_BYTES 205312

// embed_mma smem: A [64][512] bf16 = 64 KB, B 2 x 16 KB
#define EMB_OFF_B   65536
#define EMB_SMEM    98304

#define LOG2E 1.4426950408889634f

// ---------------------------------------------------------------------------
// Kernel: transpose + cvt weights to bf16 [N][K]; z==0 blocks also zero out2.
// ---------------------------------------------------------------------------
__global__ void prep_w_kernel(const float* __restrict__ Wim,
                              const float* __restrict__ Wp,
                              const float* __restrict__ Wx,
                              float* __restrict__ out)
{
    __shared__ float tile[32][33];
    const int z = blockIdx.z;
    const float* src = (z == 0) ? Wim : (z == 1) ? Wp : Wx;
    const int n0 = blockIdx.x * 32, k0 = blockIdx.y * 32;
    tile[threadIdx.y][threadIdx.x] = src[(k0 + threadIdx.y) * CC + n0 + threadIdx.x];
    if (z == 0) {
        const int idx = (blockIdx.y * 16 + blockIdx.x) * 256 + threadIdx.y * 32 + threadIdx.x;
        if (idx < BB * TT * TT) out[BB * TT * CC + idx] = 0.f;
    }
    __syncthreads();
    g_WT[(size_t)(z * CC + n0 + threadIdx.y) * CC + k0 + threadIdx.x] =
        __float2bfloat16(tile[threadIdx.x][threadIdx.y]);
}

// ---------------------------------------------------------------------------
// Kernel: embedding GEMMs on tensor cores. VE pre-scaled by log2e.
// ---------------------------------------------------------------------------
__global__ __launch_bounds__(256, 2) void embed_mma_kernel(
    const float* __restrict__ x,
    const float* __restrict__ bp, const float* __restrict__ bx)
{
    extern __shared__ char sm[];
    const uint32_t smb = smem_u32(sm);
    const int tid = threadIdx.x, lane = tid & 31, wid = tid >> 5;
    const int mt = blockIdx.x & 15, nt = blockIdx.x >> 4;
    const int r0 = mt * 64;

    auto issueB = [&](int s) {
        const int n  = tid >> 1;
        const int cq = (tid & 1) * 4;
        const uint32_t dstRow = smb + EMB_OFF_B + (s & 1) * 16384 + n * 128;
        const __nv_bfloat16* src = g_WT + (size_t)(CC + nt * 128 + n) * CC + s * 64 + cq * 8;
#pragma unroll
        for (int c = 0; c < 4; c++)
            cp_async16(dstRow + (((cq + c) ^ (n & 7)) << 4), src + c * 8);
        CP_COMMIT();
    };
    issueB(0);

    {
        const int rbase = wid * 8;
#pragma unroll
        for (int rr = 0; rr < 8; rr++) {
            const int r = rbase + rr;
            const float* xr = x + (size_t)(r0 + r) * CC;
            char* Arow = sm + r * 1024;
            const int xw = r & 7;
#pragma unroll
            for (int pass = 0; pass < 4; pass++) {
                const int k = pass * 128 + lane * 4;
                const float4 xv = *(const float4*)(xr + k);
                uint2 pk;
                ((__nv_bfloat162*)&pk)[0] = __floats2bfloat162_rn(xv.x, xv.y);
                ((__nv_bfloat162*)&pk)[1] = __floats2bfloat162_rn(xv.z, xv.w);
                const int c8 = pass * 16 + (lane >> 1);
                *(uint2*)(Arow + ((c8 ^ xw) << 4) + ((lane & 1) << 3)) = pk;
            }
        }
    }

    const int mw = wid & 1, nw = wid >> 1;
    const int mA  = mw * 32 + (lane & 15);
    const int aC8 = lane >> 4;
    const int aXr = mA & 7;
    const uint32_t aBase = smb + mA * 1024;
    const int nB  = nw * 32 + (lane & 7) + ((lane >> 4) << 3);
    const int bC8 = (lane >> 3) & 1;
    const int bXr = nB & 7;
    const uint32_t bRowOff = (uint32_t)nB * 128;

    float acc[2][4][4];
#pragma unroll
    for (int mf = 0; mf < 2; mf++)
#pragma unroll
        for (int nf = 0; nf < 4; nf++)
#pragma unroll
            for (int d = 0; d < 4; d++) acc[mf][nf][d] = 0.f;

#pragma unroll 1
    for (int s = 0; s < 8; s++) {
        CP_WAIT0();
        __syncthreads();
        if (s < 7) issueB(s + 1);
        const uint32_t Bslot = smb + EMB_OFF_B + (s & 1) * 16384;
#pragma unroll
        for (int t = 0; t < 4; t++) {
            uint32_t a0[4], a1[4], b0[4], b1[4];
            const uint32_t swA = (uint32_t)(((s * 8 + t * 2 + aC8) ^ aXr) << 4);
            ldsm4(a0, aBase + swA);
            ldsm4(a1, aBase + 16384 + swA);
            const uint32_t swB = (uint32_t)(((t * 2 + bC8) ^ bXr) << 4);
            const uint32_t bA = Bslot + bRowOff + swB;
            ldsm4(b0, bA);
            ldsm4(b1, bA + 2048);
            mma_bf16(acc[0][0], a0, b0);
            mma_bf16(acc[0][1], a0, b0 + 2);
            mma_bf16(acc[0][2], a0, b1);
            mma_bf16(acc[0][3], a0, b1 + 2);
            mma_bf16(acc[1][0], a1, b0);
            mma_bf16(acc[1][1], a1, b0 + 2);
            mma_bf16(acc[1][2], a1, b1);
            mma_bf16(acc[1][3], a1, b1 + 2);
        }
    }

    const int qrow = lane >> 2, qcol2 = (lane & 3) * 2;
    const int cbase = (nt & 3) * 128 + nw * 32;
    const float* bias = (nt < 4) ? bp : bx;
    float2 bb[4];
#pragma unroll
    for (int nf = 0; nf < 4; nf++)
        bb[nf] = *(const float2*)(bias + cbase + nf * 8 + qcol2);

    if (nt < 4) {
#pragma unroll
        for (int mf = 0; mf < 2; mf++)
#pragma unroll
            for (int h = 0; h < 2; h++) {
                const int row = r0 + mw * 32 + mf * 16 + h * 8 + qrow;
#pragma unroll
                for (int nf = 0; nf < 4; nf++) {
                    const int col = cbase + nf * 8 + qcol2;
                    *(float2*)(g_VE + (size_t)row * CC + col) =
                        make_float2((acc[mf][nf][h * 2] + bb[nf].x) * LOG2E,
                                    (acc[mf][nf][h * 2 + 1] + bb[nf].y) * LOG2E);
                }
            }
    } else {
#pragma unroll
        for (int mf = 0; mf < 2; mf++)
#pragma unroll
            for (int h = 0; h < 2; h++) {
                const int row = r0 + mw * 32 + mf * 16 + h * 8 + qrow;
#pragma unroll
                for (int nf = 0; nf < 4; nf++) {
                    const int col = cbase + nf * 8 + qcol2;
                    *(__nv_bfloat162*)(g_XEh + (size_t)row * CC + col) =
                        __floats2bfloat162_rn(acc[mf][nf][h * 2] + bb[nf].x,
                                              acc[mf][nf][h * 2 + 1] + bb[nf].y);
                }
            }
    }
}

// ---------------------------------------------------------------------------
// Main kernel: PERSISTENT, 148 CTAs x 384 threads.
// 2 groups of 6 warps: 4 MMA warps (ldsm+mma+epilogue ONLY) + 2 builder warps
// (A-stage construction ONLY), coupled by a 4-slot mbarrier ring per group.
// Builders run ahead and keep filling A during the consumers' epilogue.
// B [128 n][512 k] bf16 resident in smem (loaded once).
// ---------------------------------------------------------------------------
__global__ __launch_bounds__(384, 1) void temporal_kernel(
    const float* __restrict__ x,
    const float* __restrict__ ts,
    const float* __restrict__ amask,
    const float* __restrict__ Wt,  const float* __restrict__ bt,
    const float* __restrict__ bim,
    float* __restrict__ out)
{
    extern __shared__ char sm[];
    const uint32_t smb = smem_u32(sm);
    const int tid   = threadIdx.x;
    const int lane  = tid & 31;
    const int g     = tid / 192;         // group 0..1
    const int tid_l = tid % 192;         // 0..127 MMA, 128..191 builders

    const int chunk = blockIdx.x & 3;
    const int slot37 = blockIdx.x >> 2;  // 0..36
    const int stream = slot37 * 2 + g;   // 0..73 within this chunk
    const int ntiles = (stream < 62) ? 14 : 13;   // 1024 = 74*13 + 62

    // ---- load resident B slice [128 n][512 k], XOR-swizzled ----
    {
        const __nv_bfloat16* Bsrc = g_WT + (size_t)(chunk * 128) * CC;
#pragma unroll 4
        for (int idx = tid; idx < 8192; idx += 384) {
            const int n = idx >> 6, c8 = idx & 63;
            cp_async16(smb + OFF_B + n * 1024 + ((c8 ^ (n & 7)) << 4),
                       Bsrc + (size_t)n * CC + c8 * 8);
        }
        CP_COMMIT();
    }

    __nv_bfloat162* sWt0h = (__nv_bfloat162*)(sm + OFF_WT0);   // [256]
    __nv_bfloat162* sWt1h = (__nv_bfloat162*)(sm + OFF_WT1);
    __nv_bfloat162* sbth  = (__nv_bfloat162*)(sm + OFF_BT);
    float* sbim = (float*)(sm + OFF_BIM);
    char*  grp  = sm + OFF_GRP + g * 1536;
    uint32_t* f0b  = (uint32_t*)(grp + GRP_F0);
    uint32_t* f1b  = (uint32_t*)(grp + GRP_F1);
    float* sout2 = (float*)(grp + GRP_SOUT2);
    float* sexp  = (float*)(grp + GRP_SEXP);

    // mbarrier ring addresses
    const uint32_t mb_base = smb + OFF_MBAR + g * 64;
    auto mb_full  = [&](int s) { return mb_base + s * 16; };
    auto mb_empty = [&](int s) { return mb_base + s * 16 + 8; };

    // ---- one-time staging ----
    for (int i2 = tid; i2 < 512; i2 += 384) sbim[i2] = bim[i2];
    if (tid < 256) {
        sWt0h[tid] = __floats2bfloat162_rn(Wt[tid * 2],      Wt[tid * 2 + 1]);
        sWt1h[tid] = __floats2bfloat162_rn(Wt[CC + tid * 2], Wt[CC + tid * 2 + 1]);
        sbth[tid]  = __floats2bfloat162_rn(bt[tid * 2],      bt[tid * 2 + 1]);
    }
    if (tid_l < 128) sexp[tid_l] = 0.f;
    if (tid_l < 64)  sout2[tid_l] = 0.f;
    if (tid == 0) {
#pragma unroll
        for (int gg = 0; gg < 2; gg++)
#pragma unroll
            for (int s = 0; s < 4; s++) {
                MBAR_INIT(smb + OFF_MBAR + gg * 64 + s * 16,     64);   // full
                MBAR_INIT(smb + OFF_MBAR + gg * 64 + s * 16 + 8, 128);  // empty
            }
    }
    CP_WAIT0();
    __syncthreads();   // B + staging + mbarriers visible; roles diverge

    const int bar_mma   = 1 + g * 2;   // 128 threads
    const int bar_build = 2 + g * 2;   // 64 threads
    char* Aring = sm + OFF_A + g * 32768;   // 4 slots x 8192

    if (tid_l >= 128) {
        // =========================== BUILDERS ===========================
        const int tid_b = tid_l - 128;       // 0..63
        const int ro8   = tid_b >> 3;        // base row 0..7
        const int c8b   = tid_b & 7;         // k-octet within stage
        const uint32_t xorc = (uint32_t)((c8b ^ ro8) << 4);
        const __nv_bfloat162 zero2 = __floats2bfloat162_rn(0.f, 0.f);
        int ps = 0, pp = 1;                  // producer cursor (phase 1!)

#pragma unroll 1
        for (int t = 0; t < ntiles; t++) {
            const int idx = stream + 74 * t;
            const int b = idx >> 6, i = idx & 63;
            // f0/f1 staging (builders are sole readers)
            {
                const float rel = ts[b * TT + i] - ts[b * TT + tid_b];
                const __nv_bfloat16 h0 = __float2bfloat16_rn(log1pf(fmaxf(rel, 0.f)));
                const __nv_bfloat16 h1 = __float2bfloat16_rn(log1pf(fmaxf(-rel, 0.f)));
                __nv_bfloat162 p0 = __nv_bfloat162(h0, h0);
                __nv_bfloat162 p1 = __nv_bfloat162(h1, h1);
                f0b[tid_b] = *(uint32_t*)&p0;
                f1b[tid_b] = *(uint32_t*)&p1;
            }
            bar_named(bar_build, 64);
            const __nv_bfloat16* XEb = g_XEh + (size_t)(b * TT) * CC;

#pragma unroll 1
            for (int s = 0; s < 8; s++) {
                const int kb = s * 64 + c8b * 8;
                const int kp = (kb >> 1);
                const uint4 w0q = *(const uint4*)(sWt0h + kp);
                const uint4 w1q = *(const uint4*)(sWt1h + kp);
                const uint4 btq = *(const uint4*)(sbth + kp);
                const __nv_bfloat162* w02 = (const __nv_bfloat162*)&w0q;
                const __nv_bfloat162* w12 = (const __nv_bfloat162*)&w1q;
                const __nv_bfloat162* bt2 = (const __nv_bfloat162*)&btq;

                mbar_wait(mb_empty(ps), pp);
                char* Adst = Aring + ps * 8192;
#pragma unroll
                for (int it = 0; it < 8; it++) {
                    const int r = ro8 + it * 8;
                    const uint4 xp = *(const uint4*)(XEb + (size_t)r * CC + kb);
                    const __nv_bfloat162* xe2 = (const __nv_bfloat162*)&xp;
                    const uint32_t f0p = f0b[r], f1p = f1b[r];
                    const __nv_bfloat162 f0x2 = *(const __nv_bfloat162*)&f0p;
                    const __nv_bfloat162 f1x2 = *(const __nv_bfloat162*)&f1p;
                    uint4 pk;
                    __nv_bfloat162* p2 = (__nv_bfloat162*)&pk;
#pragma unroll
                    for (int q = 0; q < 4; q++) {
                        __nv_bfloat162 tt2 = __hadd2(bt2[q], xe2[q]);
                        tt2 = __hfma2(f1x2, w12[q], tt2);
                        tt2 = __hfma2(f0x2, w02[q], tt2);
                        p2[q] = __hmax2(tt2, zero2);
                    }
                    *(uint4*)(Adst + r * 128 + xorc) = pk;
                }
                MBAR_ARRIVE(mb_full(ps));
                if (++ps == 4) { ps = 0; pp ^= 1; }
            }
            bar_named(bar_build, 64);   // all builds done before f0b overwrite
        }
    } else {
        // =========================== MMA WARPS ===========================
        const int gw = tid_l >> 5;           // 0..3
        const int mw = gw & 1, nw = gw >> 1;
        const int m0  = mw * 32;
        const int n0w = nw * 64;
        const int mA  = m0 + (lane & 15);
        const int aC8 = lane >> 4;
        const int aXr = mA & 7;
        const int nB  = n0w + (lane & 7) + ((lane >> 4) << 3);
        const int bC8 = (lane >> 3) & 1;
        const int bXr = nB & 7;
        const uint32_t bBase = smb + OFF_B + (uint32_t)nB * 1024;
        const int qrow = lane >> 2, qcol2 = (lane & 3) * 2;

        uint32_t aOff[4], bOff[4];
#pragma unroll
        for (int tk = 0; tk < 4; tk++) {
            aOff[tk] = (uint32_t)(((tk * 2 + aC8) ^ aXr) << 4) + (uint32_t)mA * 128;
            bOff[tk] = bBase + (uint32_t)(((tk * 2 + bC8) ^ bXr) << 4);
        }

        float* gout2 = out + BB * TT * CC;
        int cs = 0, cp = 0;                  // consumer cursor (phase 0)

#pragma unroll 1
        for (int t = 0; t < ntiles; t++) {
            const int idx = stream + 74 * t;
            const int b = idx >> 6, i = idx & 63;

            float acc[2][8][4];
#pragma unroll
            for (int mf = 0; mf < 2; mf++)
#pragma unroll
                for (int nf = 0; nf < 8; nf++)
#pragma unroll
                    for (int d = 0; d < 4; d++) acc[mf][nf][d] = 0.f;

#pragma unroll 1
            for (int s = 0; s < 8; s++) {
                mbar_wait(mb_full(cs), cp);
                const uint32_t aSlot = smb + OFF_A + g * 32768 + (uint32_t)cs * 8192;
                const uint32_t bStage = (uint32_t)(s * 128);
#pragma unroll
                for (int tk = 0; tk < 4; tk++) {
                    uint32_t a0[4], a1[4], bf[4][4];
                    const uint32_t aA = aSlot + aOff[tk];
                    ldsm4(a0, aA);
                    ldsm4(a1, aA + 2048);
                    const uint32_t bA = bOff[tk] + bStage;
                    ldsm4(bf[0], bA);
                    ldsm4(bf[1], bA + 16384);
                    ldsm4(bf[2], bA + 32768);
                    ldsm4(bf[3], bA + 49152);
#pragma unroll
                    for (int qq = 0; qq < 4; qq++) {
                        mma_bf16(acc[0][qq * 2],     a0, bf[qq]);
                        mma_bf16(acc[0][qq * 2 + 1], a0, bf[qq] + 2);
                        mma_bf16(acc[1][qq * 2],     a1, bf[qq]);
                        mma_bf16(acc[1][qq * 2 + 1], a1, bf[qq] + 2);
                    }
                }
                MBAR_ARRIVE(mb_empty(cs));
                if (++cs == 4) { cs = 0; cp ^= 1; }
            }

            // ---- epilogue: sigmoid/mask, logsumexp, out2 ----
            float hmks[2][2];
#pragma unroll
            for (int mf = 0; mf < 2; mf++)
#pragma unroll
                for (int h = 0; h < 2; h++)
                    hmks[mf][h] = 0.5f * amask[b * TT + m0 + mf * 16 + h * 8 + qrow];

            float rs[4] = {0.f, 0.f, 0.f, 0.f};
#pragma unroll
            for (int nh = 0; nh < 2; nh++) {
                float bimv[8], csum[8];
#pragma unroll
                for (int nf = 0; nf < 4; nf++) {
                    bimv[nf * 2]     = sbim[chunk * 128 + n0w + nh * 32 + nf * 8 + qcol2];
                    bimv[nf * 2 + 1] = sbim[chunk * 128 + n0w + nh * 32 + nf * 8 + qcol2 + 1];
                    csum[nf * 2] = 0.f; csum[nf * 2 + 1] = 0.f;
                }
#pragma unroll
                for (int mf = 0; mf < 2; mf++) {
#pragma unroll
                    for (int h = 0; h < 2; h++) {
                        const int r  = m0 + mf * 16 + h * 8 + qrow;
                        const float hmk = hmks[mf][h];
                        const float* VEr = g_VE + (size_t)(b * TT + r) * CC
                                           + chunk * 128 + n0w + nh * 32 + qcol2;
                        float rsum = 0.f;
#pragma unroll
                        for (int nf = 0; nf < 4; nf++) {
                            const float2 ve = *(const float2*)(VEr + nf * 8);
                            const float s0 = acc[mf][nh * 4 + nf][h * 2 + 0] + bimv[nf * 2];
                            const float s1 = acc[mf][nh * 4 + nf][h * 2 + 1] + bimv[nf * 2 + 1];
                            const float p0 = fmaf(tanh_fast(0.5f * s0), hmk, hmk);
                            const float p1 = fmaf(tanh_fast(0.5f * s1), hmk, hmk);
                            rsum += p0 + p1;
                            csum[nf * 2]     += ex2_fast(ve.x * p0);
                            csum[nf * 2 + 1] += ex2_fast(ve.y * p1);
                        }
                        rs[mf * 2 + h] += rsum;
                    }
                }
#pragma unroll
                for (int c = 0; c < 8; c++) {
                    csum[c] += __shfl_xor_sync(0xffffffffu, csum[c], 4);
                    csum[c] += __shfl_xor_sync(0xffffffffu, csum[c], 8);
                    csum[c] += __shfl_xor_sync(0xffffffffu, csum[c], 16);
                }
                if (lane < 4) {
#pragma unroll
                    for (int nf = 0; nf < 4; nf++) {
                        atomicAdd(&sexp[n0w + nh * 32 + nf * 8 + lane * 2],     csum[nf * 2]);
                        atomicAdd(&sexp[n0w + nh * 32 + nf * 8 + lane * 2 + 1], csum[nf * 2 + 1]);
                    }
                }
            }
#pragma unroll
            for (int q = 0; q < 4; q++) {
                rs[q] += __shfl_xor_sync(0xffffffffu, rs[q], 1);
                rs[q] += __shfl_xor_sync(0xffffffffu, rs[q], 2);
            }
            if ((lane & 3) == 0) {
#pragma unroll
                for (int q = 0; q < 4; q++)
                    atomicAdd(&sout2[m0 + (q >> 1) * 16 + (q & 1) * 8 + qrow], rs[q]);
            }
            bar_named(bar_mma, 128);

            // outputs (128 threads)
            {
                const int ng = chunk * 128 + tid_l;
                const int row = b * TT + i;
                out[(size_t)row * CC + ng] = x[(size_t)row * CC + ng] + __logf(sexp[tid_l]);
                sexp[tid_l] = 0.f;
            }
            if (tid_l < 64) {
                atomicAdd(&gout2[(b * TT + i) * TT + tid_l], sout2[tid_l] * (1.f / 512.f));
                sout2[tid_l] = 0.f;
            }
            bar_named(bar_mma, 128);
        }
    }
}

// ---------------------------------------------------------------------------
extern "C" void kernel_launch(void* const* d_in, const int* in_sizes, int n_in,
                              void* d_out, int out_size)
{
    const float* x     = (const float*)d_in[0];
    const float* ts    = (const float*)d_in[1];
    const float* amask = (const float*)d_in[2];
    const float* Wp    = (const float*)d_in[3];
    const float* bp    = (const float*)d_in[4];
    const float* Wx    = (const float*)d_in[5];
    const float* bx    = (const float*)d_in[6];
    const float* Wt    = (const float*)d_in[7];
    const float* bt    = (const float*)d_in[8];
    const float* Wim   = (const float*)d_in[9];
    const float* bim   = (const float*)d_in[10];
    float* out = (float*)d_out;

    prep_w_kernel<<<dim3(16, 16, 3), dim3(32, 32)>>>(Wim, Wp, Wx, out);

    cudaFuncSetAttribute(embed_mma_kernel, cudaFuncAttributeMaxDynamicSharedMemorySize, EMB_SMEM);
    embed_mma_kernel<<<128, 256, EMB_SMEM>>>(x, bp, bx);

    cudaFuncSetAttribute(temporal_kernel, cudaFuncAttributeMaxDynamicSharedMemorySize, SMEM_BYTES);
    temporal_kernel<<<148, 384, SMEM_BYTES>>>(x, ts, amask, Wt, bt, bim, out);
}